// round 12
// baseline (speedup 1.0000x reference)
#include <cuda_runtime.h>
#include <cuda_fp16.h>
#include <cstdint>

#define NUM_E 100000
#define DZ    384
#define MEMD  256
#define NODED 128
#define E_PAD 100096           // 1564 * 64
#define BM 64
#define BN 64
#define KB 64
#define NCH (DZ/KB)            // 6 chunks

#define ZSTR 72
#define WSTR 72
#define ZHALVES (3*64*ZSTR)    // 13824
#define WHALVES (2*64*WSTR)    // 9216
#define STAGE_H (ZHALVES + WHALVES)
#define SMEM_BYTES (2 * STAGE_H * 2)      // 92160 B

#define NMBLK 1564
#define SM_S  68               // m-blocks per slice
#define NS    23               // 23*68 = 1564
#define GA_PER (SM_S*8)        // 544 gather blocks / slice
#define GE_PER (SM_S*6)        // 408 gemm blocks / slice
#define LAG   2
#define TOTAL_BLOCKS (NS*GA_PER + NS*GE_PER)   // 21896

__device__ __align__(16) __half g_zs[(size_t)E_PAD * DZ];
__device__ __align__(16) __half g_zp[(size_t)E_PAD * DZ];
__device__ __align__(16) __half g_zn[(size_t)E_PAD * DZ];
__device__ __align__(16) __half g_wl[DZ * DZ];
__device__ __align__(16) __half g_wd[DZ * DZ];
__device__ int   g_id3[3 * NUM_E];
__device__ float g_rt3[3 * NUM_E];
__device__ int   g_cnt[1600];

__device__ __forceinline__ void mma_f16(float* c,
    uint32_t a0, uint32_t a1, uint32_t a2, uint32_t a3,
    uint32_t b0, uint32_t b1)
{
    asm volatile(
        "mma.sync.aligned.m16n8k16.row.col.f32.f16.f16.f32 "
        "{%0,%1,%2,%3},{%4,%5,%6,%7},{%8,%9},{%0,%1,%2,%3};"
        : "+f"(c[0]), "+f"(c[1]), "+f"(c[2]), "+f"(c[3])
        : "r"(a0), "r"(a1), "r"(a2), "r"(a3), "r"(b0), "r"(b1));
}
__device__ __forceinline__ void ldsm4(uint32_t* r, uint32_t addr) {
    asm volatile("ldmatrix.sync.aligned.m8n8.x4.shared.b16 {%0,%1,%2,%3}, [%4];"
                 : "=r"(r[0]), "=r"(r[1]), "=r"(r[2]), "=r"(r[3]) : "r"(addr));
}
__device__ __forceinline__ int ld_acq(const int* p) {
    int v;
    asm volatile("ld.acquire.gpu.global.b32 %0, [%1];" : "=r"(v) : "l"(p) : "memory");
    return v;
}

// ---------------------------------------------------------------------------
// Resolve (+ weight conversion + counter reset): y in {0,1,2} = id chains,
// y == 3 = convert weights to fp16 and zero the readiness counters.
// ---------------------------------------------------------------------------
__global__ void resolve(
    const float* __restrict__ lu, const float* __restrict__ bt,
    const float* __restrict__ bfin,
    const float* __restrict__ wlf, const float* __restrict__ wdf,
    const int* __restrict__ nid, const int* __restrict__ idmap,
    const int* __restrict__ src, const int* __restrict__ pdst,
    const int* __restrict__ ndst,
    float* __restrict__ out)
{
    int e = blockIdx.x * blockDim.x + threadIdx.x;
    int w = blockIdx.y;
    if (w == 3) {
        for (int i = e; i < DZ * DZ; i += gridDim.x * blockDim.x) {
            g_wl[i] = __float2half_rn(wlf[i]);
            g_wd[i] = __float2half_rn(wdf[i]);
        }
        if (e < 1600) g_cnt[e] = 0;
        return;
    }
    if (e >= NUM_E) return;
    const int* idx = (w == 0) ? src : (w == 1) ? pdst : ndst;
    int g = nid[idmap[idx[e]]];
    g_id3[w * NUM_E + e] = g;
    g_rt3[w * NUM_E + e] = fabsf(lu[g] - bt[e]);
    if (w == 0) {
        float bfv = bfin[0];
        out[e]         = bfv;
        out[NUM_E + e] = bfv;
    }
}

// ---------------------------------------------------------------------------
// Fused gather + GEMM kernel. 1D grid, role decoded from blockIdx.x.
// Gather blocks (8 edges, warp-per-edge) fill g_z* and signal g_cnt[mblk].
// GEMM blocks (R7 champion config) spin on their m-block counter, then run
// the double-buffered KB=64 triple-GEMM + readout.
// ---------------------------------------------------------------------------
__global__ __launch_bounds__(256, 2) void fused_gg(
    const float* __restrict__ mem, const float* __restrict__ x,
    const float* __restrict__ wps, const float* __restrict__ bps,
    const float* __restrict__ wpd, const float* __restrict__ bpd,
    const float* __restrict__ bl,  const float* __restrict__ bd,
    const float* __restrict__ wf,
    float* __restrict__ out)
{
    int bid = blockIdx.x;
    int tid = threadIdx.x;

    int role, s, rr;
    const int HEAD = LAG * GA_PER;                       // 1088
    const int BODY = HEAD + (NS - LAG) * (GA_PER + GE_PER);  // 21080
    if (bid < HEAD) {
        role = 0; s = bid / GA_PER; rr = bid % GA_PER;
    } else if (bid < BODY) {
        int t = bid - HEAD;
        int k = t / (GA_PER + GE_PER);
        int r = t % (GA_PER + GE_PER);
        if (r < GA_PER) { role = 0; s = k + LAG; rr = r; }
        else            { role = 1; s = k;       rr = r - GA_PER; }
    } else {
        int t = bid - BODY;
        role = 1; s = NS - LAG + t / GE_PER; rr = t % GE_PER;
    }

    if (role == 0) {
        // ---------------- gather: 8 edges, warp-per-edge ----------------
        int g = s * GA_PER + rr;            // global gather-block index
        int lane = tid & 31;
        int e = g * 8 + (tid >> 5);

        if (e < NUM_E) {
            int gs = g_id3[e], gp = g_id3[NUM_E + e], gn = g_id3[2 * NUM_E + e];
            float rts = g_rt3[e], rtp = g_rt3[NUM_E + e], rtn = g_rt3[2 * NUM_E + e];

            const float* rs = mem + (size_t)gs * MEMD;
            const float* rp = mem + (size_t)gp * MEMD;
            const float* rn = mem + (size_t)gn * MEMD;
            float* msrc = out + 2 * NUM_E + (size_t)e * MEMD;
            float* mpos = out + 2 * NUM_E + (size_t)NUM_E * MEMD + (size_t)e * MEMD;
            size_t zoff = (size_t)e * DZ;

            #pragma unroll
            for (int j = 0; j < 3; j++) {
                int c = 4 * lane + 128 * j;

                float4 vs, vp, vn;
                if (j < 2) {
                    vs = *(const float4*)(rs + c);
                    vp = *(const float4*)(rp + c);
                    vn = *(const float4*)(rn + c);
                    *(float4*)(msrc + c) = vs;
                    *(float4*)(mpos + c) = vp;
                } else {
                    int cx = c - MEMD;
                    vs = *(const float4*)(x + (size_t)gs * NODED + cx);
                    vp = *(const float4*)(x + (size_t)gp * NODED + cx);
                    vn = *(const float4*)(x + (size_t)gn * NODED + cx);
                }

                float4 w4 = *(const float4*)(wps + c);
                float4 b4 = *(const float4*)(bps + c);
                float4 d4 = *(const float4*)(wpd + c);
                float4 e4 = *(const float4*)(bpd + c);

                float4 ss, sp, sn;
                ss.x = 1.f + rts * w4.x + b4.x; ss.y = 1.f + rts * w4.y + b4.y;
                ss.z = 1.f + rts * w4.z + b4.z; ss.w = 1.f + rts * w4.w + b4.w;
                sp.x = 1.f + rtp * d4.x + e4.x; sp.y = 1.f + rtp * d4.y + e4.y;
                sp.z = 1.f + rtp * d4.z + e4.z; sp.w = 1.f + rtp * d4.w + e4.w;
                sn.x = 1.f + rtn * d4.x + e4.x; sn.y = 1.f + rtn * d4.y + e4.y;
                sn.z = 1.f + rtn * d4.z + e4.z; sn.w = 1.f + rtn * d4.w + e4.w;

                __half2 h0, h1;
                h0 = __floats2half2_rn(vs.x * ss.x, vs.y * ss.y);
                h1 = __floats2half2_rn(vs.z * ss.z, vs.w * ss.w);
                *(uint2*)(g_zs + zoff + c) = make_uint2(*(uint32_t*)&h0, *(uint32_t*)&h1);
                h0 = __floats2half2_rn(vp.x * sp.x, vp.y * sp.y);
                h1 = __floats2half2_rn(vp.z * sp.z, vp.w * sp.w);
                *(uint2*)(g_zp + zoff + c) = make_uint2(*(uint32_t*)&h0, *(uint32_t*)&h1);
                h0 = __floats2half2_rn(vn.x * sn.x, vn.y * sn.y);
                h1 = __floats2half2_rn(vn.z * sn.z, vn.w * sn.w);
                *(uint2*)(g_zn + zoff + c) = make_uint2(*(uint32_t*)&h0, *(uint32_t*)&h1);
            }
        }
        __threadfence();
        __syncthreads();
        if (tid == 0) atomicAdd(&g_cnt[g >> 3], 1);
        return;
    }

    // ---------------- gemm: R7 champion body ----------------
    int mblk = s * SM_S + rr / 6;
    int nblk = rr % 6;
    int m0 = mblk * BM;
    int n0 = nblk * BN;

    // wait for this m-block's 8 gather blocks
    if (tid == 0) {
        while (ld_acq(&g_cnt[mblk]) < 8) __nanosleep(128);
    }
    __syncthreads();

    extern __shared__ __half sm[];
    uint32_t sbase = (uint32_t)__cvta_generic_to_shared(sm);

    int wid  = tid >> 5, lane = tid & 31;
    int grp  = lane >> 2, qid = lane & 3;
    int wm   = wid & 3,  wn  = wid >> 2;

    int rowA = wm * 16 + (lane & 15);
    int kA   = (lane >> 4) * 8;
    int rowB = wn * 32 + (lane & 7) + ((lane >> 4) & 1) * 8;
    int kB   = ((lane >> 3) & 1) * 8;

    const __half* zsrc[3] = { g_zs, g_zp, g_zn };
    const __half* wsrc[2] = { g_wl, g_wd };

    float acc[3][4][4];
    #pragma unroll
    for (int a = 0; a < 3; a++)
        #pragma unroll
        for (int b = 0; b < 4; b++)
            #pragma unroll
            for (int c = 0; c < 4; c++) acc[a][b][c] = 0.f;

    auto load_chunk = [&](int ch, int stg) {
        int k0 = ch * KB;
        uint32_t sb = sbase + (uint32_t)(stg * STAGE_H) * 2;
        #pragma unroll
        for (int p = 0; p < 6; p++) {
            int id  = tid + p * 256;
            int mat = id >> 9;
            int rem = id & 511;
            int row = rem >> 3;
            int c8  = (rem & 7) << 3;
            const __half* src = zsrc[mat] + (size_t)(m0 + row) * DZ + k0 + c8;
            uint32_t dst = sb + (uint32_t)(((mat * 64 + row) * ZSTR + c8) * 2);
            asm volatile("cp.async.cg.shared.global [%0], [%1], 16;" :: "r"(dst), "l"(src));
        }
        #pragma unroll
        for (int p = 0; p < 4; p++) {
            int id  = tid + p * 256;
            int mat = id >> 9;
            int rem = id & 511;
            int row = rem >> 3;
            int c8  = (rem & 7) << 3;
            const __half* src = wsrc[mat] + (size_t)(n0 + row) * DZ + k0 + c8;
            uint32_t dst = sb + (uint32_t)((ZHALVES + (mat * 64 + row) * WSTR + c8) * 2);
            asm volatile("cp.async.cg.shared.global [%0], [%1], 16;" :: "r"(dst), "l"(src));
        }
        asm volatile("cp.async.commit_group;");
    };

    load_chunk(0, 0);
    int stg = 0;
    for (int ch = 0; ch < NCH; ch++) {
        if (ch + 1 < NCH) {
            load_chunk(ch + 1, stg ^ 1);
            asm volatile("cp.async.wait_group 1;");
        } else {
            asm volatile("cp.async.wait_group 0;");
        }
        __syncthreads();

        uint32_t zb = sbase + (uint32_t)(stg * STAGE_H) * 2;
        uint32_t wb = zb + (uint32_t)ZHALVES * 2;

        #pragma unroll
        for (int kk = 0; kk < KB; kk += 16) {
            uint32_t afr[3][4];
            uint32_t bfr[2][2][4];
            #pragma unroll
            for (int mat = 0; mat < 3; mat++) {
                uint32_t a = zb + (uint32_t)(((mat * 64 + rowA) * ZSTR + kk + kA) * 2);
                ldsm4(afr[mat], a);
            }
            #pragma unroll
            for (int mat = 0; mat < 2; mat++)
                #pragma unroll
                for (int pr = 0; pr < 2; pr++) {
                    uint32_t a = wb + (uint32_t)(((mat * 64 + rowB + pr * 16) * WSTR + kk + kB) * 2);
                    ldsm4(bfr[mat][pr], a);
                }
            #pragma unroll
            for (int pr = 0; pr < 2; pr++)
                #pragma unroll
                for (int h = 0; h < 2; h++) {
                    int nt = pr * 2 + h;
                    mma_f16(acc[0][nt], afr[0][0], afr[0][1], afr[0][2], afr[0][3],
                            bfr[0][pr][2 * h], bfr[0][pr][2 * h + 1]);
                    mma_f16(acc[1][nt], afr[1][0], afr[1][1], afr[1][2], afr[1][3],
                            bfr[1][pr][2 * h], bfr[1][pr][2 * h + 1]);
                    mma_f16(acc[2][nt], afr[2][0], afr[2][1], afr[2][2], afr[2][3],
                            bfr[1][pr][2 * h], bfr[1][pr][2 * h + 1]);
                }
        }
        __syncthreads();
        stg ^= 1;
    }

    float pp0 = 0.f, pp1 = 0.f, pn0 = 0.f, pn1 = 0.f;
    #pragma unroll
    for (int nt = 0; nt < 4; nt++) {
        #pragma unroll
        for (int j = 0; j < 2; j++) {
            int n = n0 + wn * 32 + nt * 8 + 2 * qid + j;
            float bias = bl[n] + bd[n];
            float wfn  = wf[n];
            float c0 = acc[0][nt][j]     + acc[1][nt][j]     + bias;
            float c1 = acc[0][nt][2 + j] + acc[1][nt][2 + j] + bias;
            pp0 += fmaxf(c0, 0.f) * wfn;
            pp1 += fmaxf(c1, 0.f) * wfn;
            float d0 = acc[0][nt][j]     + acc[2][nt][j]     + bias;
            float d1 = acc[0][nt][2 + j] + acc[2][nt][2 + j] + bias;
            pn0 += fmaxf(d0, 0.f) * wfn;
            pn1 += fmaxf(d1, 0.f) * wfn;
        }
    }
    #pragma unroll
    for (int sft = 1; sft < 4; sft <<= 1) {
        pp0 += __shfl_xor_sync(0xffffffffu, pp0, sft);
        pp1 += __shfl_xor_sync(0xffffffffu, pp1, sft);
        pn0 += __shfl_xor_sync(0xffffffffu, pn0, sft);
        pn1 += __shfl_xor_sync(0xffffffffu, pn1, sft);
    }
    if (qid == 0) {
        int e0 = m0 + wm * 16 + grp;
        int e1 = e0 + 8;
        if (e0 < NUM_E) {
            atomicAdd(&out[e0],         pp0);
            atomicAdd(&out[NUM_E + e0], pn0);
        }
        if (e1 < NUM_E) {
            atomicAdd(&out[e1],         pp1);
            atomicAdd(&out[NUM_E + e1], pn1);
        }
    }
}

// ---------------------------------------------------------------------------
extern "C" void kernel_launch(void* const* d_in, const int* in_sizes, int n_in,
                              void* d_out, int out_size) {
    const float* mem  = (const float*)d_in[0];
    const float* lu   = (const float*)d_in[1];
    const float* x    = (const float*)d_in[2];
    const float* bt   = (const float*)d_in[3];
    const float* wps  = (const float*)d_in[4];
    const float* bps  = (const float*)d_in[5];
    const float* wpd  = (const float*)d_in[6];
    const float* bpd  = (const float*)d_in[7];
    const float* wl   = (const float*)d_in[8];
    const float* bl   = (const float*)d_in[9];
    const float* wd   = (const float*)d_in[10];
    const float* bd   = (const float*)d_in[11];
    const float* wf   = (const float*)d_in[12];
    const float* bf   = (const float*)d_in[13];
    const int*   nid  = (const int*)d_in[14];
    const int*   idm  = (const int*)d_in[15];
    const int*   src  = (const int*)d_in[16];
    const int*   pds  = (const int*)d_in[17];
    const int*   nds  = (const int*)d_in[18];
    float* out = (float*)d_out;

    cudaFuncSetAttribute(fused_gg,
                         cudaFuncAttributeMaxDynamicSharedMemorySize, SMEM_BYTES);

    dim3 rgrid((NUM_E + 255) / 256, 4);   // y=0..2 resolve, y=3 convw+counters
    resolve<<<rgrid, 256>>>(lu, bt, bf, wl, wd, nid, idm, src, pds, nds, out);

    fused_gg<<<TOTAL_BLOCKS, 256, SMEM_BYTES>>>(mem, x, wps, bps, wpd, bpd,
                                                bl, bd, wf, out);
}

// round 13
// speedup vs baseline: 1.0234x; 1.0234x over previous
#include <cuda_runtime.h>
#include <cuda_fp16.h>
#include <cstdint>

#define NUM_E 100000
#define DZ    384
#define MEMD  256
#define NODED 128
#define E_PAD 100096           // 1564 * 64
#define BM 64
#define BN 64
#define KB 64
#define NCH (DZ/KB)            // 6 chunks

#define ZSTR 72
#define WSTR 72
#define ZHALVES (3*64*ZSTR)    // 13824
#define WHALVES (2*64*WSTR)    // 9216
#define STAGE_H (ZHALVES + WHALVES)
#define SMEM_BYTES (2 * STAGE_H * 2)      // 92160 B

__device__ __align__(16) __half g_zs[(size_t)E_PAD * DZ];
__device__ __align__(16) __half g_zp[(size_t)E_PAD * DZ];
__device__ __align__(16) __half g_zn[(size_t)E_PAD * DZ];
__device__ __align__(16) __half g_wl[DZ * DZ];
__device__ __align__(16) __half g_wd[DZ * DZ];
__device__ int   g_id3[3 * NUM_E];
__device__ float g_rt3[3 * NUM_E];

__device__ __forceinline__ void mma_f16(float* c,
    uint32_t a0, uint32_t a1, uint32_t a2, uint32_t a3,
    uint32_t b0, uint32_t b1)
{
    asm volatile(
        "mma.sync.aligned.m16n8k16.row.col.f32.f16.f16.f32 "
        "{%0,%1,%2,%3},{%4,%5,%6,%7},{%8,%9},{%0,%1,%2,%3};"
        : "+f"(c[0]), "+f"(c[1]), "+f"(c[2]), "+f"(c[3])
        : "r"(a0), "r"(a1), "r"(a2), "r"(a3), "r"(b0), "r"(b1));
}
__device__ __forceinline__ void ldsm4(uint32_t* r, uint32_t addr) {
    asm volatile("ldmatrix.sync.aligned.m8n8.x4.shared.b16 {%0,%1,%2,%3}, [%4];"
                 : "=r"(r[0]), "=r"(r[1]), "=r"(r[2]), "=r"(r[3]) : "r"(addr));
}

// ---------------------------------------------------------------------------
// Resolve (+ weight conversion): y in {0,1,2} resolves id chains in parallel;
// y == 3 converts weights. Also seeds the scalar outputs.
// ---------------------------------------------------------------------------
__global__ void resolve(
    const float* __restrict__ lu, const float* __restrict__ bt,
    const float* __restrict__ bfin,
    const float* __restrict__ wlf, const float* __restrict__ wdf,
    const int* __restrict__ nid, const int* __restrict__ idmap,
    const int* __restrict__ src, const int* __restrict__ pdst,
    const int* __restrict__ ndst,
    float* __restrict__ out)
{
    int e = blockIdx.x * blockDim.x + threadIdx.x;
    int w = blockIdx.y;
    if (w == 3) {
        for (int i = e; i < DZ * DZ; i += gridDim.x * blockDim.x) {
            g_wl[i] = __float2half_rn(wlf[i]);
            g_wd[i] = __float2half_rn(wdf[i]);
        }
        return;
    }
    if (e >= NUM_E) return;
    const int* idx = (w == 0) ? src : (w == 1) ? pdst : ndst;
    int g = nid[idmap[idx[e]]];
    g_id3[w * NUM_E + e] = g;
    g_rt3[w * NUM_E + e] = fabsf(lu[g] - bt[e]);
    if (w == 0) {
        float bfv = bfin[0];
        out[e]         = bfv;
        out[NUM_E + e] = bfv;
    }
}

// ---------------------------------------------------------------------------
// mpass: raw memory passthrough outputs (m[i_src], m[i_pos]).
// Depends only on resolve; runs on a forked stream concurrent with
// gather + GEMM. Warp-per-edge, float4 copies.
// ---------------------------------------------------------------------------
__global__ __launch_bounds__(256) void mpass(
    const float* __restrict__ mem, float* __restrict__ out)
{
    int lane = threadIdx.x & 31;
    int e = blockIdx.x * 8 + (threadIdx.x >> 5);
    int gs = g_id3[e], gp = g_id3[NUM_E + e];
    const float* rs = mem + (size_t)gs * MEMD;
    const float* rp = mem + (size_t)gp * MEMD;
    float* msrc = out + 2 * NUM_E + (size_t)e * MEMD;
    float* mpos = out + 2 * NUM_E + (size_t)NUM_E * MEMD + (size_t)e * MEMD;
    #pragma unroll
    for (int j = 0; j < 2; j++) {
        int c = 4 * lane + 128 * j;
        *(float4*)(msrc + c) = *(const float4*)(rs + c);
        *(float4*)(mpos + c) = *(const float4*)(rp + c);
    }
}

// ---------------------------------------------------------------------------
// Gather: 96 threads per edge, float4 loads, half2 packed stores.
// (passthrough removed -> on critical path only z production remains)
// ---------------------------------------------------------------------------
__global__ __launch_bounds__(96) void gather96(
    const float* __restrict__ mem, const float* __restrict__ x,
    const float* __restrict__ wps, const float* __restrict__ bps,
    const float* __restrict__ wpd, const float* __restrict__ bpd)
{
    int e = blockIdx.x;
    int t = threadIdx.x;
    int c = t * 4;
    bool isMem = (c < MEMD);

    int gs = g_id3[e], gp = g_id3[NUM_E + e], gn = g_id3[2 * NUM_E + e];
    float rts = g_rt3[e], rtp = g_rt3[NUM_E + e], rtn = g_rt3[2 * NUM_E + e];

    float4 ws4 = *(const float4*)(wps + c);
    float4 bs4 = *(const float4*)(bps + c);
    float4 wd4 = *(const float4*)(wpd + c);
    float4 bd4 = *(const float4*)(bpd + c);

    float4 ss, sp, sn;
    ss.x = 1.f + rts * ws4.x + bs4.x; ss.y = 1.f + rts * ws4.y + bs4.y;
    ss.z = 1.f + rts * ws4.z + bs4.z; ss.w = 1.f + rts * ws4.w + bs4.w;
    sp.x = 1.f + rtp * wd4.x + bd4.x; sp.y = 1.f + rtp * wd4.y + bd4.y;
    sp.z = 1.f + rtp * wd4.z + bd4.z; sp.w = 1.f + rtp * wd4.w + bd4.w;
    sn.x = 1.f + rtn * wd4.x + bd4.x; sn.y = 1.f + rtn * wd4.y + bd4.y;
    sn.z = 1.f + rtn * wd4.z + bd4.z; sn.w = 1.f + rtn * wd4.w + bd4.w;

    float4 vs, vp, vn;
    if (isMem) {
        vs = *(const float4*)(mem + (size_t)gs * MEMD + c);
        vp = *(const float4*)(mem + (size_t)gp * MEMD + c);
        vn = *(const float4*)(mem + (size_t)gn * MEMD + c);
    } else {
        int cx = c - MEMD;
        vs = *(const float4*)(x + (size_t)gs * NODED + cx);
        vp = *(const float4*)(x + (size_t)gp * NODED + cx);
        vn = *(const float4*)(x + (size_t)gn * NODED + cx);
    }

    size_t off = (size_t)e * DZ + c;
    {
        __half2 h0 = __floats2half2_rn(vs.x * ss.x, vs.y * ss.y);
        __half2 h1 = __floats2half2_rn(vs.z * ss.z, vs.w * ss.w);
        *(uint2*)(g_zs + off) = make_uint2(*(uint32_t*)&h0, *(uint32_t*)&h1);
    }
    {
        __half2 h0 = __floats2half2_rn(vp.x * sp.x, vp.y * sp.y);
        __half2 h1 = __floats2half2_rn(vp.z * sp.z, vp.w * sp.w);
        *(uint2*)(g_zp + off) = make_uint2(*(uint32_t*)&h0, *(uint32_t*)&h1);
    }
    {
        __half2 h0 = __floats2half2_rn(vn.x * sn.x, vn.y * sn.y);
        __half2 h1 = __floats2half2_rn(vn.z * sn.z, vn.w * sn.w);
        *(uint2*)(g_zn + off) = make_uint2(*(uint32_t*)&h0, *(uint32_t*)&h1);
    }
}

// ---------------------------------------------------------------------------
// Kernel B (R7 champion, verbatim): fused triple fp16 GEMM + readout.
// ---------------------------------------------------------------------------
__global__ __launch_bounds__(256, 2) void gemm_readout(
    const float* __restrict__ bl, const float* __restrict__ bd,
    const float* __restrict__ wf,
    float* __restrict__ out)
{
    extern __shared__ __half sm[];
    uint32_t sbase = (uint32_t)__cvta_generic_to_shared(sm);

    int tid  = threadIdx.x;
    int wid  = tid >> 5, lane = tid & 31;
    int grp  = lane >> 2, qid = lane & 3;
    int wm   = wid & 3,  wn  = wid >> 2;
    int m0   = blockIdx.y * BM;
    int n0   = blockIdx.x * BN;

    int rowA = wm * 16 + (lane & 15);
    int kA   = (lane >> 4) * 8;
    int rowB = wn * 32 + (lane & 7) + ((lane >> 4) & 1) * 8;
    int kB   = ((lane >> 3) & 1) * 8;

    const __half* zsrc[3] = { g_zs, g_zp, g_zn };
    const __half* wsrc[2] = { g_wl, g_wd };

    float acc[3][4][4];
    #pragma unroll
    for (int a = 0; a < 3; a++)
        #pragma unroll
        for (int b = 0; b < 4; b++)
            #pragma unroll
            for (int c = 0; c < 4; c++) acc[a][b][c] = 0.f;

    auto load_chunk = [&](int ch, int stg) {
        int k0 = ch * KB;
        uint32_t sb = sbase + (uint32_t)(stg * STAGE_H) * 2;
        #pragma unroll
        for (int p = 0; p < 6; p++) {
            int id  = tid + p * 256;
            int mat = id >> 9;
            int rem = id & 511;
            int row = rem >> 3;
            int c8  = (rem & 7) << 3;
            const __half* src = zsrc[mat] + (size_t)(m0 + row) * DZ + k0 + c8;
            uint32_t dst = sb + (uint32_t)(((mat * 64 + row) * ZSTR + c8) * 2);
            asm volatile("cp.async.cg.shared.global [%0], [%1], 16;" :: "r"(dst), "l"(src));
        }
        #pragma unroll
        for (int p = 0; p < 4; p++) {
            int id  = tid + p * 256;
            int mat = id >> 9;
            int rem = id & 511;
            int row = rem >> 3;
            int c8  = (rem & 7) << 3;
            const __half* src = wsrc[mat] + (size_t)(n0 + row) * DZ + k0 + c8;
            uint32_t dst = sb + (uint32_t)((ZHALVES + (mat * 64 + row) * WSTR + c8) * 2);
            asm volatile("cp.async.cg.shared.global [%0], [%1], 16;" :: "r"(dst), "l"(src));
        }
        asm volatile("cp.async.commit_group;");
    };

    load_chunk(0, 0);
    int stg = 0;
    for (int ch = 0; ch < NCH; ch++) {
        if (ch + 1 < NCH) {
            load_chunk(ch + 1, stg ^ 1);
            asm volatile("cp.async.wait_group 1;");
        } else {
            asm volatile("cp.async.wait_group 0;");
        }
        __syncthreads();

        uint32_t zb = sbase + (uint32_t)(stg * STAGE_H) * 2;
        uint32_t wb = zb + (uint32_t)ZHALVES * 2;

        #pragma unroll
        for (int kk = 0; kk < KB; kk += 16) {
            uint32_t afr[3][4];
            uint32_t bfr[2][2][4];
            #pragma unroll
            for (int mat = 0; mat < 3; mat++) {
                uint32_t a = zb + (uint32_t)(((mat * 64 + rowA) * ZSTR + kk + kA) * 2);
                ldsm4(afr[mat], a);
            }
            #pragma unroll
            for (int mat = 0; mat < 2; mat++)
                #pragma unroll
                for (int pr = 0; pr < 2; pr++) {
                    uint32_t a = wb + (uint32_t)(((mat * 64 + rowB + pr * 16) * WSTR + kk + kB) * 2);
                    ldsm4(bfr[mat][pr], a);
                }
            #pragma unroll
            for (int pr = 0; pr < 2; pr++)
                #pragma unroll
                for (int h = 0; h < 2; h++) {
                    int nt = pr * 2 + h;
                    mma_f16(acc[0][nt], afr[0][0], afr[0][1], afr[0][2], afr[0][3],
                            bfr[0][pr][2 * h], bfr[0][pr][2 * h + 1]);
                    mma_f16(acc[1][nt], afr[1][0], afr[1][1], afr[1][2], afr[1][3],
                            bfr[1][pr][2 * h], bfr[1][pr][2 * h + 1]);
                    mma_f16(acc[2][nt], afr[2][0], afr[2][1], afr[2][2], afr[2][3],
                            bfr[1][pr][2 * h], bfr[1][pr][2 * h + 1]);
                }
        }
        __syncthreads();
        stg ^= 1;
    }

    float pp0 = 0.f, pp1 = 0.f, pn0 = 0.f, pn1 = 0.f;
    #pragma unroll
    for (int nt = 0; nt < 4; nt++) {
        #pragma unroll
        for (int j = 0; j < 2; j++) {
            int n = n0 + wn * 32 + nt * 8 + 2 * qid + j;
            float bias = bl[n] + bd[n];
            float wfn  = wf[n];
            float c0 = acc[0][nt][j]     + acc[1][nt][j]     + bias;
            float c1 = acc[0][nt][2 + j] + acc[1][nt][2 + j] + bias;
            pp0 += fmaxf(c0, 0.f) * wfn;
            pp1 += fmaxf(c1, 0.f) * wfn;
            float d0 = acc[0][nt][j]     + acc[2][nt][j]     + bias;
            float d1 = acc[0][nt][2 + j] + acc[2][nt][2 + j] + bias;
            pn0 += fmaxf(d0, 0.f) * wfn;
            pn1 += fmaxf(d1, 0.f) * wfn;
        }
    }
    #pragma unroll
    for (int s = 1; s < 4; s <<= 1) {
        pp0 += __shfl_xor_sync(0xffffffffu, pp0, s);
        pp1 += __shfl_xor_sync(0xffffffffu, pp1, s);
        pn0 += __shfl_xor_sync(0xffffffffu, pn0, s);
        pn1 += __shfl_xor_sync(0xffffffffu, pn1, s);
    }
    if (qid == 0) {
        int e0 = m0 + wm * 16 + grp;
        int e1 = e0 + 8;
        if (e0 < NUM_E) {
            atomicAdd(&out[e0],         pp0);
            atomicAdd(&out[NUM_E + e0], pn0);
        }
        if (e1 < NUM_E) {
            atomicAdd(&out[e1],         pp1);
            atomicAdd(&out[NUM_E + e1], pn1);
        }
    }
}

// ---------------------------------------------------------------------------
extern "C" void kernel_launch(void* const* d_in, const int* in_sizes, int n_in,
                              void* d_out, int out_size) {
    const float* mem  = (const float*)d_in[0];
    const float* lu   = (const float*)d_in[1];
    const float* x    = (const float*)d_in[2];
    const float* bt   = (const float*)d_in[3];
    const float* wps  = (const float*)d_in[4];
    const float* bps  = (const float*)d_in[5];
    const float* wpd  = (const float*)d_in[6];
    const float* bpd  = (const float*)d_in[7];
    const float* wl   = (const float*)d_in[8];
    const float* bl   = (const float*)d_in[9];
    const float* wd   = (const float*)d_in[10];
    const float* bd   = (const float*)d_in[11];
    const float* wf   = (const float*)d_in[12];
    const float* bf   = (const float*)d_in[13];
    const int*   nid  = (const int*)d_in[14];
    const int*   idm  = (const int*)d_in[15];
    const int*   src  = (const int*)d_in[16];
    const int*   pds  = (const int*)d_in[17];
    const int*   nds  = (const int*)d_in[18];
    float* out = (float*)d_out;

    static cudaStream_t s2 = nullptr;
    static cudaEvent_t  evFork = nullptr, evJoin = nullptr;
    if (s2 == nullptr) {
        cudaStreamCreateWithFlags(&s2, cudaStreamNonBlocking);
        cudaEventCreateWithFlags(&evFork, cudaEventDisableTiming);
        cudaEventCreateWithFlags(&evJoin, cudaEventDisableTiming);
        cudaFuncSetAttribute(gemm_readout,
                             cudaFuncAttributeMaxDynamicSharedMemorySize, SMEM_BYTES);
    }

    dim3 rgrid((NUM_E + 255) / 256, 4);   // y=0..2 resolve, y=3 convw
    resolve<<<rgrid, 256>>>(lu, bt, bf, wl, wd, nid, idm, src, pds, nds, out);

    // fork: mpass depends only on resolve; overlaps gather + GEMM
    cudaEventRecord(evFork, 0);
    cudaStreamWaitEvent(s2, evFork, 0);
    mpass<<<NUM_E / 8, 256, 0, s2>>>(mem, out);

    gather96<<<NUM_E, 96>>>(mem, x, wps, bps, wpd, bpd);

    dim3 grid(DZ / BN, E_PAD / BM);   // (6, 1564)
    gemm_readout<<<grid, 256, SMEM_BYTES>>>(bl, bd, wf, out);

    // join
    cudaEventRecord(evJoin, s2);
    cudaStreamWaitEvent(0, evJoin, 0);
}

// round 14
// speedup vs baseline: 1.0619x; 1.0377x over previous
#include <cuda_runtime.h>
#include <cuda_fp16.h>
#include <cstdint>

#define NUM_E 100000
#define DZ    384
#define MEMD  256
#define NODED 128
#define E_PAD 100096           // 1564 * 64
#define BM 64
#define BN 64
#define KB 64
#define NCH (DZ/KB)            // 6 chunks

#define ZSTR 72
#define WSTR 72
#define ZHALVES (3*64*ZSTR)    // 13824
#define WHALVES (2*64*WSTR)    // 9216
#define STAGE_H (ZHALVES + WHALVES)
#define SMEM_BYTES (2 * STAGE_H * 2)      // 92160 B

__device__ __align__(16) __half g_zs[(size_t)E_PAD * DZ];
__device__ __align__(16) __half g_zp[(size_t)E_PAD * DZ];
__device__ __align__(16) __half g_zn[(size_t)E_PAD * DZ];
__device__ __align__(16) __half g_wl[DZ * DZ];
__device__ __align__(16) __half g_wd[DZ * DZ];
__device__ int   g_id3[3 * NUM_E];
__device__ float g_rt3[3 * NUM_E];

__device__ __forceinline__ void mma_f16(float* c,
    uint32_t a0, uint32_t a1, uint32_t a2, uint32_t a3,
    uint32_t b0, uint32_t b1)
{
    asm volatile(
        "mma.sync.aligned.m16n8k16.row.col.f32.f16.f16.f32 "
        "{%0,%1,%2,%3},{%4,%5,%6,%7},{%8,%9},{%0,%1,%2,%3};"
        : "+f"(c[0]), "+f"(c[1]), "+f"(c[2]), "+f"(c[3])
        : "r"(a0), "r"(a1), "r"(a2), "r"(a3), "r"(b0), "r"(b1));
}
__device__ __forceinline__ void ldsm4(uint32_t* r, uint32_t addr) {
    asm volatile("ldmatrix.sync.aligned.m8n8.x4.shared.b16 {%0,%1,%2,%3}, [%4];"
                 : "=r"(r[0]), "=r"(r[1]), "=r"(r[2]), "=r"(r[3]) : "r"(addr));
}

// ---------------------------------------------------------------------------
// Resolve (+ weight conversion): y in {0,1,2} resolves id chains in parallel;
// y == 3 converts weights. Also seeds the scalar outputs with b_final.
// ---------------------------------------------------------------------------
__global__ void resolve(
    const float* __restrict__ lu, const float* __restrict__ bt,
    const float* __restrict__ bfin,
    const float* __restrict__ wlf, const float* __restrict__ wdf,
    const int* __restrict__ nid, const int* __restrict__ idmap,
    const int* __restrict__ src, const int* __restrict__ pdst,
    const int* __restrict__ ndst,
    float* __restrict__ out)
{
    int e = blockIdx.x * blockDim.x + threadIdx.x;
    int w = blockIdx.y;
    if (w == 3) {
        for (int i = e; i < DZ * DZ; i += gridDim.x * blockDim.x) {
            g_wl[i] = __float2half_rn(wlf[i]);
            g_wd[i] = __float2half_rn(wdf[i]);
        }
        return;
    }
    if (e >= NUM_E) return;
    const int* idx = (w == 0) ? src : (w == 1) ? pdst : ndst;
    int g = nid[idmap[idx[e]]];
    g_id3[w * NUM_E + e] = g;
    g_rt3[w * NUM_E + e] = fabsf(lu[g] - bt[e]);
    if (w == 0) {
        float bfv = bfin[0];
        out[e]         = bfv;
        out[NUM_E + e] = bfv;
    }
}

// ---------------------------------------------------------------------------
// Gather: 96 threads per edge, float4 loads, half2 packed stores.
// Passthrough outputs removed (handled inside GEMM, hidden under HMMA).
// ---------------------------------------------------------------------------
__global__ __launch_bounds__(96) void gather96(
    const float* __restrict__ mem, const float* __restrict__ x,
    const float* __restrict__ wps, const float* __restrict__ bps,
    const float* __restrict__ wpd, const float* __restrict__ bpd)
{
    int e = blockIdx.x;
    int t = threadIdx.x;
    int c = t * 4;
    bool isMem = (c < MEMD);

    int gs = g_id3[e], gp = g_id3[NUM_E + e], gn = g_id3[2 * NUM_E + e];
    float rts = g_rt3[e], rtp = g_rt3[NUM_E + e], rtn = g_rt3[2 * NUM_E + e];

    float4 ws4 = *(const float4*)(wps + c);
    float4 bs4 = *(const float4*)(bps + c);
    float4 wd4 = *(const float4*)(wpd + c);
    float4 bd4 = *(const float4*)(bpd + c);

    float4 ss, sp, sn;
    ss.x = 1.f + rts * ws4.x + bs4.x; ss.y = 1.f + rts * ws4.y + bs4.y;
    ss.z = 1.f + rts * ws4.z + bs4.z; ss.w = 1.f + rts * ws4.w + bs4.w;
    sp.x = 1.f + rtp * wd4.x + bd4.x; sp.y = 1.f + rtp * wd4.y + bd4.y;
    sp.z = 1.f + rtp * wd4.z + bd4.z; sp.w = 1.f + rtp * wd4.w + bd4.w;
    sn.x = 1.f + rtn * wd4.x + bd4.x; sn.y = 1.f + rtn * wd4.y + bd4.y;
    sn.z = 1.f + rtn * wd4.z + bd4.z; sn.w = 1.f + rtn * wd4.w + bd4.w;

    float4 vs, vp, vn;
    if (isMem) {
        vs = *(const float4*)(mem + (size_t)gs * MEMD + c);
        vp = *(const float4*)(mem + (size_t)gp * MEMD + c);
        vn = *(const float4*)(mem + (size_t)gn * MEMD + c);
    } else {
        int cx = c - MEMD;
        vs = *(const float4*)(x + (size_t)gs * NODED + cx);
        vp = *(const float4*)(x + (size_t)gp * NODED + cx);
        vn = *(const float4*)(x + (size_t)gn * NODED + cx);
    }

    size_t off = (size_t)e * DZ + c;
    {
        __half2 h0 = __floats2half2_rn(vs.x * ss.x, vs.y * ss.y);
        __half2 h1 = __floats2half2_rn(vs.z * ss.z, vs.w * ss.w);
        *(uint2*)(g_zs + off) = make_uint2(*(uint32_t*)&h0, *(uint32_t*)&h1);
    }
    {
        __half2 h0 = __floats2half2_rn(vp.x * sp.x, vp.y * sp.y);
        __half2 h1 = __floats2half2_rn(vp.z * sp.z, vp.w * sp.w);
        *(uint2*)(g_zp + off) = make_uint2(*(uint32_t*)&h0, *(uint32_t*)&h1);
    }
    {
        __half2 h0 = __floats2half2_rn(vn.x * sn.x, vn.y * sn.y);
        __half2 h1 = __floats2half2_rn(vn.z * sn.z, vn.w * sn.w);
        *(uint2*)(g_zn + off) = make_uint2(*(uint32_t*)&h0, *(uint32_t*)&h1);
    }
}

// ---------------------------------------------------------------------------
// Kernel B: R7 champion GEMM + passthrough copy hidden under HMMA.
// nblk==0 CTA of each m-block emits m[i_src]; nblk==1 emits m[i_pos].
// Per chunk: 3 LDG.128 issued before the kk-loop, stores after it.
// ---------------------------------------------------------------------------
__global__ __launch_bounds__(256, 2) void gemm_readout(
    const float* __restrict__ mem,
    const float* __restrict__ bl, const float* __restrict__ bd,
    const float* __restrict__ wf,
    float* __restrict__ out)
{
    extern __shared__ __half sm[];
    uint32_t sbase = (uint32_t)__cvta_generic_to_shared(sm);

    int tid  = threadIdx.x;
    int wid  = tid >> 5, lane = tid & 31;
    int grp  = lane >> 2, qid = lane & 3;
    int wm   = wid & 3,  wn  = wid >> 2;
    int m0   = blockIdx.y * BM;
    int n0   = blockIdx.x * BN;

    // passthrough role: nblk 0 -> m[i_src], nblk 1 -> m[i_pos]
    int which = blockIdx.x;
    bool doPT = (which < 2);
    float* ptdst = out + 2 * NUM_E + (size_t)which * NUM_E * MEMD;

    int rowA = wm * 16 + (lane & 15);
    int kA   = (lane >> 4) * 8;
    int rowB = wn * 32 + (lane & 7) + ((lane >> 4) & 1) * 8;
    int kB   = ((lane >> 3) & 1) * 8;

    const __half* zsrc[3] = { g_zs, g_zp, g_zn };
    const __half* wsrc[2] = { g_wl, g_wd };

    float acc[3][4][4];
    #pragma unroll
    for (int a = 0; a < 3; a++)
        #pragma unroll
        for (int b = 0; b < 4; b++)
            #pragma unroll
            for (int c = 0; c < 4; c++) acc[a][b][c] = 0.f;

    auto load_chunk = [&](int ch, int stg) {
        int k0 = ch * KB;
        uint32_t sb = sbase + (uint32_t)(stg * STAGE_H) * 2;
        #pragma unroll
        for (int p = 0; p < 6; p++) {
            int id  = tid + p * 256;
            int mat = id >> 9;
            int rem = id & 511;
            int row = rem >> 3;
            int c8  = (rem & 7) << 3;
            const __half* src = zsrc[mat] + (size_t)(m0 + row) * DZ + k0 + c8;
            uint32_t dst = sb + (uint32_t)(((mat * 64 + row) * ZSTR + c8) * 2);
            asm volatile("cp.async.cg.shared.global [%0], [%1], 16;" :: "r"(dst), "l"(src));
        }
        #pragma unroll
        for (int p = 0; p < 4; p++) {
            int id  = tid + p * 256;
            int mat = id >> 9;
            int rem = id & 511;
            int row = rem >> 3;
            int c8  = (rem & 7) << 3;
            const __half* src = wsrc[mat] + (size_t)(n0 + row) * DZ + k0 + c8;
            uint32_t dst = sb + (uint32_t)((ZHALVES + (mat * 64 + row) * WSTR + c8) * 2);
            asm volatile("cp.async.cg.shared.global [%0], [%1], 16;" :: "r"(dst), "l"(src));
        }
        asm volatile("cp.async.commit_group;");
    };

    load_chunk(0, 0);
    int stg = 0;
    for (int ch = 0; ch < NCH; ch++) {
        if (ch + 1 < NCH) {
            load_chunk(ch + 1, stg ^ 1);
            asm volatile("cp.async.wait_group 1;");
        } else {
            asm volatile("cp.async.wait_group 0;");
        }
        __syncthreads();

        // passthrough loads for this chunk: pieces p = ch*3 + q (p < 16)
        float4 ptv[3];
        bool ptok[3] = {false, false, false};
        if (doPT) {
            #pragma unroll
            for (int q = 0; q < 3; q++) {
                int p = ch * 3 + q;
                if (p < 16) {
                    int f = p * 256 + tid;          // float4 index in [0,4096)
                    int e = m0 + (f >> 6);
                    int c4 = (f & 63) * 4;
                    if (e < NUM_E) {
                        int gid = g_id3[which * NUM_E + e];
                        ptv[q] = *(const float4*)(mem + (size_t)gid * MEMD + c4);
                        ptok[q] = true;
                    }
                }
            }
        }

        uint32_t zb = sbase + (uint32_t)(stg * STAGE_H) * 2;
        uint32_t wb = zb + (uint32_t)ZHALVES * 2;

        #pragma unroll
        for (int kk = 0; kk < KB; kk += 16) {
            uint32_t afr[3][4];
            uint32_t bfr[2][2][4];
            #pragma unroll
            for (int mat = 0; mat < 3; mat++) {
                uint32_t a = zb + (uint32_t)(((mat * 64 + rowA) * ZSTR + kk + kA) * 2);
                ldsm4(afr[mat], a);
            }
            #pragma unroll
            for (int mat = 0; mat < 2; mat++)
                #pragma unroll
                for (int pr = 0; pr < 2; pr++) {
                    uint32_t a = wb + (uint32_t)(((mat * 64 + rowB + pr * 16) * WSTR + kk + kB) * 2);
                    ldsm4(bfr[mat][pr], a);
                }
            #pragma unroll
            for (int pr = 0; pr < 2; pr++)
                #pragma unroll
                for (int h = 0; h < 2; h++) {
                    int nt = pr * 2 + h;
                    mma_f16(acc[0][nt], afr[0][0], afr[0][1], afr[0][2], afr[0][3],
                            bfr[0][pr][2 * h], bfr[0][pr][2 * h + 1]);
                    mma_f16(acc[1][nt], afr[1][0], afr[1][1], afr[1][2], afr[1][3],
                            bfr[1][pr][2 * h], bfr[1][pr][2 * h + 1]);
                    mma_f16(acc[2][nt], afr[2][0], afr[2][1], afr[2][2], afr[2][3],
                            bfr[1][pr][2 * h], bfr[1][pr][2 * h + 1]);
                }
        }

        // passthrough stores (data long arrived; hidden under the kk loop)
        if (doPT) {
            #pragma unroll
            for (int q = 0; q < 3; q++) {
                if (ptok[q]) {
                    int p = ch * 3 + q;
                    int f = p * 256 + tid;
                    int e = m0 + (f >> 6);
                    int c4 = (f & 63) * 4;
                    *(float4*)(ptdst + (size_t)e * MEMD + c4) = ptv[q];
                }
            }
        }

        __syncthreads();
        stg ^= 1;
    }

    float pp0 = 0.f, pp1 = 0.f, pn0 = 0.f, pn1 = 0.f;
    #pragma unroll
    for (int nt = 0; nt < 4; nt++) {
        #pragma unroll
        for (int j = 0; j < 2; j++) {
            int n = n0 + wn * 32 + nt * 8 + 2 * qid + j;
            float bias = bl[n] + bd[n];
            float wfn  = wf[n];
            float c0 = acc[0][nt][j]     + acc[1][nt][j]     + bias;
            float c1 = acc[0][nt][2 + j] + acc[1][nt][2 + j] + bias;
            pp0 += fmaxf(c0, 0.f) * wfn;
            pp1 += fmaxf(c1, 0.f) * wfn;
            float d0 = acc[0][nt][j]     + acc[2][nt][j]     + bias;
            float d1 = acc[0][nt][2 + j] + acc[2][nt][2 + j] + bias;
            pn0 += fmaxf(d0, 0.f) * wfn;
            pn1 += fmaxf(d1, 0.f) * wfn;
        }
    }
    #pragma unroll
    for (int s = 1; s < 4; s <<= 1) {
        pp0 += __shfl_xor_sync(0xffffffffu, pp0, s);
        pp1 += __shfl_xor_sync(0xffffffffu, pp1, s);
        pn0 += __shfl_xor_sync(0xffffffffu, pn0, s);
        pn1 += __shfl_xor_sync(0xffffffffu, pn1, s);
    }
    if (qid == 0) {
        int e0 = m0 + wm * 16 + grp;
        int e1 = e0 + 8;
        if (e0 < NUM_E) {
            atomicAdd(&out[e0],         pp0);
            atomicAdd(&out[NUM_E + e0], pn0);
        }
        if (e1 < NUM_E) {
            atomicAdd(&out[e1],         pp1);
            atomicAdd(&out[NUM_E + e1], pn1);
        }
    }
}

// ---------------------------------------------------------------------------
extern "C" void kernel_launch(void* const* d_in, const int* in_sizes, int n_in,
                              void* d_out, int out_size) {
    const float* mem  = (const float*)d_in[0];
    const float* lu   = (const float*)d_in[1];
    const float* x    = (const float*)d_in[2];
    const float* bt   = (const float*)d_in[3];
    const float* wps  = (const float*)d_in[4];
    const float* bps  = (const float*)d_in[5];
    const float* wpd  = (const float*)d_in[6];
    const float* bpd  = (const float*)d_in[7];
    const float* wl   = (const float*)d_in[8];
    const float* bl   = (const float*)d_in[9];
    const float* wd   = (const float*)d_in[10];
    const float* bd   = (const float*)d_in[11];
    const float* wf   = (const float*)d_in[12];
    const float* bf   = (const float*)d_in[13];
    const int*   nid  = (const int*)d_in[14];
    const int*   idm  = (const int*)d_in[15];
    const int*   src  = (const int*)d_in[16];
    const int*   pds  = (const int*)d_in[17];
    const int*   nds  = (const int*)d_in[18];
    float* out = (float*)d_out;

    cudaFuncSetAttribute(gemm_readout,
                         cudaFuncAttributeMaxDynamicSharedMemorySize, SMEM_BYTES);

    dim3 rgrid((NUM_E + 255) / 256, 4);   // y=0..2 resolve, y=3 convw
    resolve<<<rgrid, 256>>>(lu, bt, bf, wl, wd, nid, idm, src, pds, nds, out);

    gather96<<<NUM_E, 96>>>(mem, x, wps, bps, wpd, bpd);

    dim3 grid(DZ / BN, E_PAD / BM);   // (6, 1564)
    gemm_readout<<<grid, 256, SMEM_BYTES>>>(mem, bl, bd, wf, out);
}